// round 15
// baseline (speedup 1.0000x reference)
#include <cuda_runtime.h>
#include <cuda_fp16.h>
#include <cstdint>

// ---------------------------------------------------------------------------
// Fused two-tower scorer, round 14: W is never staged through smem. B
// fragments are LDG.128'd directly from the pre-permuted fp16 scratch
// (512 KB, L2-resident; 16 KB/chunk working set L1-cacheable). Only the
// gathered A tile goes through smem (LDG->cvt fp16->STS, double buffered,
// one barrier per 64-K super-chunk). TB=64, 512 thr, 2 CTAs/SM, fp16
// m16n8k16, warp tile 16x64, user latent in smem.
// ---------------------------------------------------------------------------

#define NTHREADS 512
#define TB       64      // batch rows per CTA
#define LOUT     256     // latents (GEMM N)
#define KF       512     // features (GEMM K)
#define NSUPER   16      // super-chunks of 64 K (8 per tower x 2 towers)
#define PLA      1024    // A plane stride (uints) = 64 rows x 16
#define ULST     264     // user-latent smem stride (halves)

// smem byte offsets
#define S_IDXU   0                       // 64 ints
#define S_IDXI   256
#define S_UB     512                     // 256 f32
#define S_IB     1536
#define S_PART   2560                    // 64 f32
#define S_ULAT   3584                    // 64 x 264 half = 33792
#define S_A      37376                   // A: 2 super-buffers x 2 planes
#define A_BYTES  (2 * PLA * 4)           // 8192 per super-buffer
#define S_TOTAL  (S_A + 2 * A_BYTES)     // 53760 -> 2 CTAs/SM

// pre-converted, permuted fp16 weights, per-half-chunk contiguous:
// index = tower*65536 + lc*4096 + l*16 + pos   (lc = local half-chunk 0..15)
// pos = 4t + 2s + b for pair q = 8s + 4b + t   (k = lc*32 + 2q, 2q+1)
__device__ uint32_t wscr[2 * 16 * LOUT * 16];    // 131072 uints = 512 KB

// --------------------------- helpers ----------------------------------------

__device__ __forceinline__ void mma16(float* c, uint32_t a0, uint32_t a1,
                                      uint32_t a2, uint32_t a3,
                                      uint32_t b0, uint32_t b1) {
    asm volatile(
        "mma.sync.aligned.m16n8k16.row.col.f32.f16.f16.f32 "
        "{%0,%1,%2,%3}, {%4,%5,%6,%7}, {%8,%9}, {%0,%1,%2,%3};"
        : "+f"(c[0]), "+f"(c[1]), "+f"(c[2]), "+f"(c[3])
        : "r"(a0), "r"(a1), "r"(a2), "r"(a3), "r"(b0), "r"(b1));
}

__device__ __forceinline__ uint32_t h2u(__half2 h) {
    return *reinterpret_cast<uint32_t*>(&h);
}

// pos(q) = 4*(q&3) + 2*(q>>3) + ((q>>2)&1)   (within one 16-pair plane)
__device__ __forceinline__ int posof(int q) {
    return ((q & 3) << 2) | ((q >> 3) << 1) | ((q >> 2) & 1);
}

// A super-chunk: 64 rows x 16 float4 = 1024 segs / 512 thr = 2 per thread
__device__ __forceinline__ void ldg_a(float4* pref, const float* lut,
                                      const int* idx, int kc, int tid) {
#pragma unroll
    for (int i = 0; i < 2; i++) {
        int seg = tid + i * NTHREADS;
        int row = seg >> 4, q = seg & 15;
        pref[i] = __ldg(reinterpret_cast<const float4*>(
            lut + (size_t)idx[row] * KF + kc + q * 4));
    }
}

// store A super-chunk as fp16 pairs: seg q: plane h=q>>3, local pairs 2(q&7)
__device__ __forceinline__ void sts_a(const float4* pref, char* smem, int s,
                                      int tid) {
    uint32_t* base = (uint32_t*)(smem + S_A + (s & 1) * A_BYTES);
#pragma unroll
    for (int i = 0; i < 2; i++) {
        int seg = tid + i * NTHREADS;
        int row = seg >> 4, q = seg & 15;
        int h = q >> 3, qq = q & 7;
        uint32_t* rp = base + h * PLA + row * 16;
        rp[posof(2 * qq)]     = h2u(__floats2half2_rn(pref[i].x, pref[i].y));
        rp[posof(2 * qq + 1)] = h2u(__floats2half2_rn(pref[i].z, pref[i].w));
    }
}

// --------------------------- prep kernel ------------------------------------

__global__ void prep_kernel(const float* __restrict__ uW,
                            const float* __restrict__ iW) {
    int o = blockIdx.x * 256 + threadIdx.x;        // [0, 131072)
    int tower = o >> 16;                           // 0..1
    int r = o & 65535;
    int lc = r >> 12;                              // local half-chunk 0..15
    int l  = (r >> 4) & (LOUT - 1);
    int pos = r & 15;
    int t = pos >> 2, s = (pos >> 1) & 1, b = pos & 1;
    int q = 8 * s + 4 * b + t;
    const float* W = (tower ? iW : uW) + (size_t)l * KF + lc * 32 + 2 * q;
    wscr[o] = h2u(__floats2half2_rn(W[0], W[1]));
}

// --------------------------- main kernel ------------------------------------

__global__ void __launch_bounds__(NTHREADS, 2) towers_kernel(
    const int* __restrict__ x,
    const float* __restrict__ ulut, const float* __restrict__ ilut,
    const float* __restrict__ ubias, const float* __restrict__ ibias,
    float* __restrict__ out) {
    extern __shared__ char smem[];
    const int tid  = threadIdx.x;
    const int lane = tid & 31;
    const int wid  = tid >> 5;
    const int wm   = wid & 3;        // 4 row groups of 16
    const int wn   = wid >> 2;       // 4 col groups of 64
    const int g    = lane >> 2;
    const int t    = lane & 3;

    int*   idxu = (int*)(smem + S_IDXU);
    int*   idxi = (int*)(smem + S_IDXI);
    float* ubS  = (float*)(smem + S_UB);
    float* ibS  = (float*)(smem + S_IB);
    float* part = (float*)(smem + S_PART);
    __half* ulat = (__half*)(smem + S_ULAT);

    if (tid < LOUT) {
        ubS[tid] = ubias[tid];
        ibS[tid] = ibias[tid];
    }
    if (tid < TB) {
        part[tid] = 0.f;
        int gg = blockIdx.x * TB + tid;
        idxu[tid] = x[2 * gg];
        idxi[tid] = x[2 * gg + 1];
    }
    __syncthreads();

    float4 pref[2];
    ldg_a(pref, ulut, idxu, 0, tid);

    float acc[8][4];
#pragma unroll
    for (int nt = 0; nt < 8; nt++)
#pragma unroll
        for (int i = 0; i < 4; i++) acc[nt][i] = 0.f;

    const int rlo = wm * 16 + g;             // fragment rows within tile
    const int rhi = wm * 16 + 8 + g;

    for (int s = 0; s < NSUPER; s++) {
        // 1. store prefetched A super-chunk (buffer s&1); its previous
        //    readers (MMA(s-2)) completed before barrier(s-1).
        sts_a(pref, smem, s, tid);

        // 2. prefetch next A super-chunk
        if (s + 1 < NSUPER) {
            int s2 = s + 1;
            bool t2 = (s2 >= NSUPER / 2);
            ldg_a(pref, t2 ? ilut : ulut, t2 ? idxi : idxu,
                  (s2 & 7) * 64, tid);
        }

        // 3. A tile ready CTA-wide
        __syncthreads();

        const uint32_t* A =
            (const uint32_t*)(smem + S_A + (s & 1) * A_BYTES);
        const uint32_t* wt =
            wscr + ((s >= NSUPER / 2) ? 65536 : 0) + (s & 7) * 8192;

        // 4. MMA planes; B fragments LDG'd straight from wscr (L1-resident)
#pragma unroll
        for (int h = 0; h < 2; h++) {
            const uint32_t* Ah = A + h * PLA;
            const uint32_t* Bh = wt + h * 4096;
            uint4 alo = *(const uint4*)(Ah + rlo * 16 + 4 * t);
            uint4 ahi = *(const uint4*)(Ah + rhi * 16 + 4 * t);
#pragma unroll
            for (int ntb = 0; ntb < 4; ntb++) {      // 2 n-tiles at a time
                const int n0 = wn * 64 + ntb * 16 + g;
                uint4 bv0 = __ldg((const uint4*)(Bh + n0 * 16 + 4 * t));
                uint4 bv1 = __ldg((const uint4*)(Bh + (n0 + 8) * 16 + 4 * t));
                // kstep 0: x,y ; kstep 1: z,w
                mma16(acc[ntb * 2],     alo.x, ahi.x, alo.y, ahi.y,
                      bv0.x, bv0.y);
                mma16(acc[ntb * 2 + 1], alo.x, ahi.x, alo.y, ahi.y,
                      bv1.x, bv1.y);
                mma16(acc[ntb * 2],     alo.z, ahi.z, alo.w, ahi.w,
                      bv0.z, bv0.w);
                mma16(acc[ntb * 2 + 1], alo.z, ahi.z, alo.w, ahi.w,
                      bv1.z, bv1.w);
            }
        }

        // 5. user-tower epilogue: bias + relu -> fp16 smem, reset acc
        if (s == NSUPER / 2 - 1) {
#pragma unroll
            for (int nt = 0; nt < 8; nt++) {
                const int c0 = wn * 64 + nt * 8 + 2 * t;
                float u0 = fmaxf(acc[nt][0] + ubS[c0],     0.f);
                float u1 = fmaxf(acc[nt][1] + ubS[c0 + 1], 0.f);
                float u2 = fmaxf(acc[nt][2] + ubS[c0],     0.f);
                float u3 = fmaxf(acc[nt][3] + ubS[c0 + 1], 0.f);
                *(__half2*)(ulat + rlo * ULST + c0) = __floats2half2_rn(u0, u1);
                *(__half2*)(ulat + rhi * ULST + c0) = __floats2half2_rn(u2, u3);
                acc[nt][0] = acc[nt][1] = acc[nt][2] = acc[nt][3] = 0.f;
            }
        }
    }

    // item-tower epilogue: bias+relu, product with user latent, row-reduce
    {
        float s0 = 0.f, s1 = 0.f;
#pragma unroll
        for (int nt = 0; nt < 8; nt++) {
            const int c0 = wn * 64 + nt * 8 + 2 * t;
            float v0 = fmaxf(acc[nt][0] + ibS[c0],     0.f);
            float v1 = fmaxf(acc[nt][1] + ibS[c0 + 1], 0.f);
            float v2 = fmaxf(acc[nt][2] + ibS[c0],     0.f);
            float v3 = fmaxf(acc[nt][3] + ibS[c0 + 1], 0.f);
            float2 u01 = __half22float2(*(__half2*)(ulat + rlo * ULST + c0));
            float2 u23 = __half22float2(*(__half2*)(ulat + rhi * ULST + c0));
            s0 = fmaf(u01.x, v0, fmaf(u01.y, v1, s0));
            s1 = fmaf(u23.x, v2, fmaf(u23.y, v3, s1));
        }
        s0 += __shfl_xor_sync(0xffffffffu, s0, 1);
        s0 += __shfl_xor_sync(0xffffffffu, s0, 2);
        s1 += __shfl_xor_sync(0xffffffffu, s1, 1);
        s1 += __shfl_xor_sync(0xffffffffu, s1, 2);
        if (t == 0) {
            atomicAdd(&part[rlo], s0);
            atomicAdd(&part[rhi], s1);
        }
    }
    __syncthreads();

    if (tid < TB) out[blockIdx.x * TB + tid] = part[tid];
}

// --------------------------- launch -----------------------------------------

extern "C" void kernel_launch(void* const* d_in, const int* in_sizes, int n_in,
                              void* d_out, int out_size) {
    const int* x      = (const int*)d_in[0];
    const float* ulut = (const float*)d_in[1];
    const float* ilut = (const float*)d_in[2];
    const float* uW   = (const float*)d_in[3];
    const float* ub   = (const float*)d_in[4];
    const float* iW   = (const float*)d_in[5];
    const float* ib   = (const float*)d_in[6];
    float* out        = (float*)d_out;

    prep_kernel<<<2 * 16 * LOUT * 16 / 256, 256>>>(uW, iW);

    cudaFuncSetAttribute(towers_kernel,
                         cudaFuncAttributeMaxDynamicSharedMemorySize, S_TOTAL);
    int grid = out_size / TB;   // 16384 / 64 = 256
    towers_kernel<<<grid, NTHREADS, S_TOTAL>>>(x, ulut, ilut, ub, ib, out);
}